// round 1
// baseline (speedup 1.0000x reference)
#include <cuda_runtime.h>
#include <math.h>

#define BATCH 4
#define SEQ   4096
#define DIM   1024
#define NCLS  4

// ---- scratch (allocation-free: __device__ globals) ----
__device__ float g_Q[BATCH * SEQ * DIM];                 // 64 MB
__device__ float g_K[BATCH * SEQ * DIM];                 // 64 MB
__device__ float g_V[BATCH * SEQ * DIM];                 // 64 MB
__device__ float g_S[(size_t)BATCH * SEQ * SEQ];         // 256 MB
__device__ float g_w[BATCH * SEQ];
__device__ float g_pool[BATCH * DIM];

// ============================================================================
// SGEMM NN:  C[M,N] = A[M,K] @ B[K,N] + bias[N]
// BM=BN=128, BK=16, TM=TN=8, 256 threads
// ============================================================================
__global__ __launch_bounds__(256) void sgemm_nn_bias(
    int M, int N, int K,
    const float* __restrict__ A, const float* __restrict__ B,
    const float* __restrict__ bias, float* __restrict__ C)
{
    __shared__ float As[16][128];
    __shared__ float Bs[16][128];

    const int tid = threadIdx.x;
    const int cRow = blockIdx.y;   // M tile
    const int cCol = blockIdx.x;   // N tile

    const int threadCol = tid % 16;    // 16 cols of 8
    const int threadRow = tid / 16;    // 16 rows of 8

    // A loads: 128 rows x 16 cols, float4 along K. 64 rows per pass, 2 passes.
    const int aRow = tid / 4;          // 0..63
    const int aCol = (tid % 4) * 4;    // 0,4,8,12
    // B loads: 16 rows x 128 cols, float4 along N. 8 rows per pass, 2 passes.
    const int bRow = tid / 32;         // 0..7
    const int bCol = (tid % 32) * 4;   // 0..124

    const float* Aptr = A + (size_t)(cRow * 128) * K;
    const float* Bptr = B + cCol * 128;

    float acc[8][8];
#pragma unroll
    for (int i = 0; i < 8; i++)
#pragma unroll
        for (int j = 0; j < 8; j++) acc[i][j] = 0.0f;

    for (int k0 = 0; k0 < K; k0 += 16) {
#pragma unroll
        for (int r = 0; r < 128; r += 64) {
            float4 v = *(const float4*)(Aptr + (size_t)(aRow + r) * K + k0 + aCol);
            As[aCol + 0][aRow + r] = v.x;
            As[aCol + 1][aRow + r] = v.y;
            As[aCol + 2][aRow + r] = v.z;
            As[aCol + 3][aRow + r] = v.w;
        }
#pragma unroll
        for (int r = 0; r < 16; r += 8) {
            float4 v = *(const float4*)(Bptr + (size_t)(k0 + bRow + r) * N + bCol);
            *(float4*)&Bs[bRow + r][bCol] = v;
        }
        __syncthreads();

#pragma unroll
        for (int k = 0; k < 16; k++) {
            float regM[8], regN[8];
#pragma unroll
            for (int i = 0; i < 8; i++) regM[i] = As[k][threadRow * 8 + i];
#pragma unroll
            for (int j = 0; j < 8; j++) regN[j] = Bs[k][threadCol * 8 + j];
#pragma unroll
            for (int i = 0; i < 8; i++)
#pragma unroll
                for (int j = 0; j < 8; j++) acc[i][j] = fmaf(regM[i], regN[j], acc[i][j]);
        }
        __syncthreads();
    }

    const int rowBase = cRow * 128 + threadRow * 8;
    const int colBase = cCol * 128 + threadCol * 8;
#pragma unroll
    for (int i = 0; i < 8; i++) {
#pragma unroll
        for (int j4 = 0; j4 < 8; j4 += 4) {
            float4 o;
            o.x = acc[i][j4 + 0] + bias[colBase + j4 + 0];
            o.y = acc[i][j4 + 1] + bias[colBase + j4 + 1];
            o.z = acc[i][j4 + 2] + bias[colBase + j4 + 2];
            o.w = acc[i][j4 + 3] + bias[colBase + j4 + 3];
            *(float4*)(C + (size_t)(rowBase + i) * N + colBase + j4) = o;
        }
    }
}

// ============================================================================
// SGEMM NT (scores):  C[M,N] = alpha * A[M,K] @ B[N,K]^T     (per-batch via z)
// ============================================================================
__global__ __launch_bounds__(256) void sgemm_nt_scaled(
    int M, int N, int K, float alpha,
    const float* __restrict__ A, const float* __restrict__ B,
    float* __restrict__ C,
    size_t sA, size_t sB, size_t sC)
{
    const int bz = blockIdx.z;
    A += (size_t)bz * sA;
    B += (size_t)bz * sB;
    C += (size_t)bz * sC;

    __shared__ float As[16][128];
    __shared__ float Bs[16][128];

    const int tid = threadIdx.x;
    const int cRow = blockIdx.y;
    const int cCol = blockIdx.x;

    const int threadCol = tid % 16;
    const int threadRow = tid / 16;

    const int aRow = tid / 4;          // 0..63
    const int aCol = (tid % 4) * 4;

    const float* Aptr = A + (size_t)(cRow * 128) * K;
    const float* Bptr = B + (size_t)(cCol * 128) * K;   // B is N x K row-major

    float acc[8][8];
#pragma unroll
    for (int i = 0; i < 8; i++)
#pragma unroll
        for (int j = 0; j < 8; j++) acc[i][j] = 0.0f;

    for (int k0 = 0; k0 < K; k0 += 16) {
#pragma unroll
        for (int r = 0; r < 128; r += 64) {
            float4 v = *(const float4*)(Aptr + (size_t)(aRow + r) * K + k0 + aCol);
            As[aCol + 0][aRow + r] = v.x;
            As[aCol + 1][aRow + r] = v.y;
            As[aCol + 2][aRow + r] = v.z;
            As[aCol + 3][aRow + r] = v.w;
        }
#pragma unroll
        for (int r = 0; r < 128; r += 64) {
            float4 v = *(const float4*)(Bptr + (size_t)(aRow + r) * K + k0 + aCol);
            Bs[aCol + 0][aRow + r] = v.x;
            Bs[aCol + 1][aRow + r] = v.y;
            Bs[aCol + 2][aRow + r] = v.z;
            Bs[aCol + 3][aRow + r] = v.w;
        }
        __syncthreads();

#pragma unroll
        for (int k = 0; k < 16; k++) {
            float regM[8], regN[8];
#pragma unroll
            for (int i = 0; i < 8; i++) regM[i] = As[k][threadRow * 8 + i];
#pragma unroll
            for (int j = 0; j < 8; j++) regN[j] = Bs[k][threadCol * 8 + j];
#pragma unroll
            for (int i = 0; i < 8; i++)
#pragma unroll
                for (int j = 0; j < 8; j++) acc[i][j] = fmaf(regM[i], regN[j], acc[i][j]);
        }
        __syncthreads();
    }

    const int rowBase = cRow * 128 + threadRow * 8;
    const int colBase = cCol * 128 + threadCol * 8;
#pragma unroll
    for (int i = 0; i < 8; i++) {
#pragma unroll
        for (int j4 = 0; j4 < 8; j4 += 4) {
            float4 o;
            o.x = alpha * acc[i][j4 + 0];
            o.y = alpha * acc[i][j4 + 1];
            o.z = alpha * acc[i][j4 + 2];
            o.w = alpha * acc[i][j4 + 3];
            *(float4*)(C + (size_t)(rowBase + i) * N + colBase + j4) = o;
        }
    }
}

// ============================================================================
// Row softmax in-place over S rows of length SEQ. One CTA per row.
// ============================================================================
__global__ __launch_bounds__(256) void softmax_rows(float* __restrict__ S)
{
    __shared__ float buf[SEQ];
    __shared__ float red[256];

    const int tid = threadIdx.x;
    float* p = S + (size_t)blockIdx.x * SEQ;

    float lmax = -1e30f;
    for (int i = tid; i < SEQ; i += 256) {
        float v = p[i];
        buf[i] = v;
        lmax = fmaxf(lmax, v);
    }
    red[tid] = lmax;
    __syncthreads();
#pragma unroll
    for (int s = 128; s > 0; s >>= 1) {
        if (tid < s) red[tid] = fmaxf(red[tid], red[tid + s]);
        __syncthreads();
    }
    const float m = red[0];
    __syncthreads();

    float lsum = 0.0f;
    for (int i = tid; i < SEQ; i += 256) {
        float e = __expf(buf[i] - m);
        buf[i] = e;
        lsum += e;
    }
    red[tid] = lsum;
    __syncthreads();
#pragma unroll
    for (int s = 128; s > 0; s >>= 1) {
        if (tid < s) red[tid] += red[tid + s];
        __syncthreads();
    }
    const float inv = 1.0f / red[0];

    for (int i = tid; i < SEQ; i += 256)
        p[i] = buf[i] * inv;
}

// ============================================================================
// Column mean: w[b,m] = (1/SEQ) * sum_n P[b,n,m]
// ============================================================================
__global__ __launch_bounds__(256) void col_mean(const float* __restrict__ S,
                                                float* __restrict__ w)
{
    const int b = blockIdx.y;
    const int m = blockIdx.x * 256 + threadIdx.x;
    const float* p = S + (size_t)b * SEQ * SEQ + m;
    float s0 = 0.f, s1 = 0.f, s2 = 0.f, s3 = 0.f;
    for (int n = 0; n < SEQ; n += 4) {
        s0 += p[(size_t)(n + 0) * SEQ];
        s1 += p[(size_t)(n + 1) * SEQ];
        s2 += p[(size_t)(n + 2) * SEQ];
        s3 += p[(size_t)(n + 3) * SEQ];
    }
    w[b * SEQ + m] = (s0 + s1 + s2 + s3) * (1.0f / SEQ);
}

// ============================================================================
// pooled[b,d] = sum_m w[b,m] * V[b,m,d]
// ============================================================================
__global__ __launch_bounds__(256) void weighted_v(const float* __restrict__ V,
                                                  const float* __restrict__ w,
                                                  float* __restrict__ pool)
{
    const int b = blockIdx.y;
    const int d = blockIdx.x * 256 + threadIdx.x;
    const float* vp = V + (size_t)b * SEQ * DIM + d;
    const float* wp = w + b * SEQ;
    float a0 = 0.f, a1 = 0.f, a2 = 0.f, a3 = 0.f;
    for (int m = 0; m < SEQ; m += 4) {
        a0 = fmaf(wp[m + 0], vp[(size_t)(m + 0) * DIM], a0);
        a1 = fmaf(wp[m + 1], vp[(size_t)(m + 1) * DIM], a1);
        a2 = fmaf(wp[m + 2], vp[(size_t)(m + 2) * DIM], a2);
        a3 = fmaf(wp[m + 3], vp[(size_t)(m + 3) * DIM], a3);
    }
    pool[b * DIM + d] = (a0 + a1) + (a2 + a3);
}

// ============================================================================
// logits[b,c] = relu(pooled[b,:] @ Wc[:,c] + bc[c])
// ============================================================================
__global__ void classify(const float* __restrict__ pool,
                         const float* __restrict__ Wc,
                         const float* __restrict__ bc,
                         float* __restrict__ out)
{
    const int t = threadIdx.x;
    if (t >= BATCH * NCLS) return;
    const int b = t / NCLS, c = t % NCLS;
    float acc = bc[c];
    for (int d = 0; d < DIM; d++)
        acc = fmaf(pool[b * DIM + d], Wc[d * NCLS + c], acc);
    out[t] = fmaxf(acc, 0.0f);
}

// ============================================================================
extern "C" void kernel_launch(void* const* d_in, const int* in_sizes, int n_in,
                              void* d_out, int out_size)
{
    const float* x  = (const float*)d_in[0];
    const float* Wk = (const float*)d_in[1];
    const float* bk = (const float*)d_in[2];
    const float* Wq = (const float*)d_in[3];
    const float* bq = (const float*)d_in[4];
    const float* Wv = (const float*)d_in[5];
    const float* bv = (const float*)d_in[6];
    const float* Wc = (const float*)d_in[7];
    const float* bc = (const float*)d_in[8];
    float* out = (float*)d_out;

    float *Q, *K, *V, *S, *w, *pool;
    cudaGetSymbolAddress((void**)&Q, g_Q);
    cudaGetSymbolAddress((void**)&K, g_K);
    cudaGetSymbolAddress((void**)&V, g_V);
    cudaGetSymbolAddress((void**)&S, g_S);
    cudaGetSymbolAddress((void**)&w, g_w);
    cudaGetSymbolAddress((void**)&pool, g_pool);

    const int M = BATCH * SEQ;   // 16384

    // 1) QKV projections (x flattened to [B*N, D])
    dim3 gProj(DIM / 128, M / 128);
    sgemm_nn_bias<<<gProj, 256>>>(M, DIM, DIM, x, Wq, bq, Q);
    sgemm_nn_bias<<<gProj, 256>>>(M, DIM, DIM, x, Wk, bk, K);
    sgemm_nn_bias<<<gProj, 256>>>(M, DIM, DIM, x, Wv, bv, V);

    // 2) S = (Q @ K^T) / sqrt(D), per batch
    dim3 gS(SEQ / 128, SEQ / 128, BATCH);
    sgemm_nt_scaled<<<gS, 256>>>(SEQ, SEQ, DIM, 1.0f / 32.0f,
                                 Q, K, S,
                                 (size_t)SEQ * DIM, (size_t)SEQ * DIM,
                                 (size_t)SEQ * SEQ);

    // 3) row softmax in place
    softmax_rows<<<BATCH * SEQ, 256>>>(S);

    // 4) w[b,m] = column mean of attention (replaces the whole P@V GEMM:
    //    mean_n(P@V) == (mean_n P) @ V exactly)
    col_mean<<<dim3(SEQ / 256, BATCH), 256>>>(S, w);

    // 5) pooled[b,d] = sum_m w[b,m] V[b,m,d]
    weighted_v<<<dim3(DIM / 256, BATCH), 256>>>(V, w, pool);

    // 6) classifier
    classify<<<1, 32>>>(pool, Wc, bc, out);
}

// round 12
// speedup vs baseline: 1.7912x; 1.7912x over previous
#include <cuda_runtime.h>
#include <cuda_bf16.h>
#include <cstdint>
#include <math.h>

typedef __nv_bfloat16 bf16;

#define BATCH 4
#define SEQ   4096
#define KDIM  1024
#define NCLS  4

#define BK     32
#define NCH    (KDIM / BK)        // 32 k-chunks
#define SROW   40                 // padded smem row: 40 bf16 = 80 B (conflict-free)
#define TILEB  (128 * SROW * 2)   // 10240 B per tile
#define BUFB   (4 * TILEB)        // Ah, Al, Bh, Bl
#define GSMEM  (2 * BUFB)         // 81920 B double buffered

// ---------------- scratch (allocation-free __device__ globals) --------------
__device__ bf16  g_xh[BATCH * SEQ * KDIM];
__device__ bf16  g_xl[BATCH * SEQ * KDIM];
__device__ bf16  g_wth[KDIM * KDIM];
__device__ bf16  g_wtl[KDIM * KDIM];
__device__ bf16  g_Qh[BATCH * SEQ * KDIM];
__device__ bf16  g_Ql[BATCH * SEQ * KDIM];
__device__ bf16  g_Kh[BATCH * SEQ * KDIM];
__device__ bf16  g_Kl[BATCH * SEQ * KDIM];
__device__ float g_V[BATCH * SEQ * KDIM];
__device__ float g_S[(size_t)BATCH * SEQ * SEQ];
__device__ float g_rowmax[BATCH * SEQ];
__device__ float g_rowinv[BATCH * SEQ];
__device__ float g_w[BATCH * SEQ];
__device__ float g_pool[BATCH * KDIM];

// ---------------- helpers ---------------------------------------------------
__device__ __forceinline__ uint32_t smem_u32(const void* p) {
    uint32_t a;
    asm("{ .reg .u64 t; cvta.to.shared.u64 t, %1; cvt.u32.u64 %0, t; }"
        : "=r"(a) : "l"(p));
    return a;
}

__device__ __forceinline__ void ldsm4(uint32_t r[4], uint32_t a) {
    asm volatile("ldmatrix.sync.aligned.m8n8.x4.shared.b16 {%0,%1,%2,%3}, [%4];"
                 : "=r"(r[0]), "=r"(r[1]), "=r"(r[2]), "=r"(r[3]) : "r"(a));
}

__device__ __forceinline__ void mma_bf16(float c[4], const uint32_t a[4],
                                         uint32_t b0, uint32_t b1) {
    asm volatile(
        "mma.sync.aligned.m16n8k16.row.col.f32.bf16.bf16.f32 "
        "{%0,%1,%2,%3}, {%4,%5,%6,%7}, {%8,%9}, {%0,%1,%2,%3};"
        : "+f"(c[0]), "+f"(c[1]), "+f"(c[2]), "+f"(c[3])
        : "r"(a[0]), "r"(a[1]), "r"(a[2]), "r"(a[3]), "r"(b0), "r"(b1));
}

// ============================================================================
// C[m,n] = epilogue( sum_k A[m,k]*B[n,k] ) via bf16 hi/lo x3 on mma.sync HMMA.
// mode 0: acc + bias[n] -> split hi/lo bf16 to Ch/Cl   (Q/K projection)
// mode 1: acc + bias[n] -> fp32 Cf                     (V projection)
// mode 2: alpha * acc   -> fp32 Cf                     (scores)
// ============================================================================
__global__ __launch_bounds__(256)
void gemm_bf16x3(const bf16* __restrict__ Ah, const bf16* __restrict__ Al,
                 const bf16* __restrict__ Bh, const bf16* __restrict__ Bl,
                 int ldc, size_t strideA, size_t strideB, size_t strideC,
                 const float* __restrict__ bias, float alpha, int mode,
                 float* __restrict__ Cf, bf16* __restrict__ Ch, bf16* __restrict__ Cl)
{
    extern __shared__ char sm[];
    const uint32_t sb = smem_u32(sm);
    const int tid = threadIdx.x, lid = tid & 31, wid = tid >> 5;
    const int z = blockIdx.z;
    const int m0 = blockIdx.y * 128, n0 = blockIdx.x * 128;
    const int wm = wid & 3, wn = wid >> 2;            // warp tile 32(m) x 64(n)
    const int l15 = lid & 15, lh = lid >> 4;

    const bf16* gp0 = Ah + (size_t)z * strideA + (size_t)m0 * KDIM;
    const bf16* gp1 = Al + (size_t)z * strideA + (size_t)m0 * KDIM;
    const bf16* gp2 = Bh + (size_t)z * strideB + (size_t)n0 * KDIM;
    const bf16* gp3 = Bl + (size_t)z * strideB + (size_t)n0 * KDIM;

    // per-thread load geometry: 2 uint4 per tile, v = tid + j*256
    const int row0 = tid >> 2;               // v=tid     : row 0..63
    const int row1 = (tid + 256) >> 2;       // v=tid+256 : row 64..127
    const int cB   = (tid & 3) * 8;          // bf16 elem offset of 16B vector
    const int so0  = row0 * SROW + cB;       // smem elem offsets
    const int so1  = row1 * SROW + cB;

    float acc[16][4];
#pragma unroll
    for (int f = 0; f < 16; f++)
#pragma unroll
        for (int c = 0; c < 4; c++) acc[f][c] = 0.0f;

    // preload chunk 0 into buffer 0
    {
        char* d = sm;
        *(uint4*)(d + 0 * TILEB + so0 * 2) = *(const uint4*)(gp0 + (size_t)row0 * KDIM + cB);
        *(uint4*)(d + 0 * TILEB + so1 * 2) = *(const uint4*)(gp0 + (size_t)row1 * KDIM + cB);
        *(uint4*)(d + 1 * TILEB + so0 * 2) = *(const uint4*)(gp1 + (size_t)row0 * KDIM + cB);
        *(uint4*)(d + 1 * TILEB + so1 * 2) = *(const uint4*)(gp1 + (size_t)row1 * KDIM + cB);
        *(uint4*)(d + 2 * TILEB + so0 * 2) = *(const uint4*)(gp2 + (size_t)row0 * KDIM + cB);
        *(uint4*)(d + 2 * TILEB + so1 * 2) = *(const uint4*)(gp2 + (size_t)row1 * KDIM + cB);
        *(uint4*)(d + 3 * TILEB + so0 * 2) = *(const uint4*)(gp3 + (size_t)row0 * KDIM + cB);
        *(uint4*)(d + 3 * TILEB + so1 * 2) = *(const uint4*)(gp3 + (size_t)row1 * KDIM + cB);
    }
    __syncthreads();

#pragma unroll 1
    for (int i = 0; i < NCH; i++) {
        const int cur = i & 1;
        uint4 pf[8];
        const bool more = (i + 1 < NCH);
        if (more) {
            const size_t kb = (size_t)(i + 1) * BK + cB;
            pf[0] = *(const uint4*)(gp0 + (size_t)row0 * KDIM + kb);
            pf[1] = *(const uint4*)(gp0 + (size_t)row1 * KDIM + kb);
            pf[2] = *(const uint4*)(gp1 + (size_t)row0 * KDIM + kb);
            pf[3] = *(const uint4*)(gp1 + (size_t)row1 * KDIM + kb);
            pf[4] = *(const uint4*)(gp2 + (size_t)row0 * KDIM + kb);
            pf[5] = *(const uint4*)(gp2 + (size_t)row1 * KDIM + kb);
            pf[6] = *(const uint4*)(gp3 + (size_t)row0 * KDIM + kb);
            pf[7] = *(const uint4*)(gp3 + (size_t)row1 * KDIM + kb);
        }

        const uint32_t bc = sb + cur * BUFB;
#pragma unroll
        for (int ks = 0; ks < 2; ks++) {
            const int k0 = ks * 16;
            uint32_t ah[2][4], al[2][4], bh[4][4], bl[4][4];
#pragma unroll
            for (int mi = 0; mi < 2; mi++) {
                uint32_t ao = bc + ((wm * 32 + mi * 16 + l15) * SROW + k0 + lh * 8) * 2;
                ldsm4(ah[mi], ao);
                ldsm4(al[mi], ao + TILEB);
            }
#pragma unroll
            for (int nq = 0; nq < 4; nq++) {
                uint32_t bo = bc + 2 * TILEB +
                              ((wn * 64 + nq * 16 + l15) * SROW + k0 + lh * 8) * 2;
                ldsm4(bh[nq], bo);
                ldsm4(bl[nq], bo + TILEB);
            }
#pragma unroll
            for (int mi = 0; mi < 2; mi++)
#pragma unroll
                for (int nq = 0; nq < 4; nq++) {
                    float* c0 = acc[mi * 8 + nq * 2 + 0];
                    float* c1 = acc[mi * 8 + nq * 2 + 1];
                    mma_bf16(c0, ah[mi], bh[nq][0], bh[nq][2]);
                    mma_bf16(c1, ah[mi], bh[nq][1], bh[nq][3]);
                    mma_bf16(c0, al[mi], bh[nq][0], bh[nq][2]);
                    mma_bf16(c1, al[mi], bh[nq][1], bh[nq][3]);
                    mma_bf16(c0, ah[mi], bl[nq][0], bl[nq][2]);
                    mma_bf16(c1, ah[mi], bl[nq][1], bl[nq][3]);
                }
        }

        if (more) {
            char* d = sm + (cur ^ 1) * BUFB;
            *(uint4*)(d + 0 * TILEB + so0 * 2) = pf[0];
            *(uint4*)(d + 0 * TILEB + so1 * 2) = pf[1];
            *(uint4*)(d + 1 * TILEB + so0 * 2) = pf[2];
            *(uint4*)(d + 1 * TILEB + so1 * 2) = pf[3];
            *(uint4*)(d + 2 * TILEB + so0 * 2) = pf[4];
            *(uint4*)(d + 2 * TILEB + so1 * 2) = pf[5];
            *(uint4*)(d + 3 * TILEB + so0 * 2) = pf[6];
            *(uint4*)(d + 3 * TILEB + so1 * 2) = pf[7];
        }
        __syncthreads();
    }

    // ---------------- epilogue ----------------
    const int qr = lid >> 2;            // 0..7
    const int qc = (lid & 3) * 2;       // 0,2,4,6

#pragma unroll
    for (int mi = 0; mi < 2; mi++) {
#pragma unroll
        for (int nj = 0; nj < 8; nj++) {
            const float* c = acc[mi * 8 + nj];
            const int m = m0 + wm * 32 + mi * 16 + qr;
            const int n = n0 + wn * 64 + nj * 8 + qc;
            if (mode == 2) {
                float* dst = Cf + (size_t)z * strideC;
                float2 v0 = make_float2(alpha * c[0], alpha * c[1]);
                float2 v1 = make_float2(alpha * c[2], alpha * c[3]);
                *(float2*)(dst + (size_t)m * ldc + n) = v0;
                *(float2*)(dst + (size_t)(m + 8) * ldc + n) = v1;
            } else if (mode == 1) {
                const float b0 = bias[n], b1 = bias[n + 1];
                *(float2*)(Cf + (size_t)m * ldc + n) = make_float2(c[0] + b0, c[1] + b1);
                *(float2*)(Cf + (size_t)(m + 8) * ldc + n) = make_float2(c[2] + b0, c[3] + b1);
            } else {
                const float b0 = bias[n], b1 = bias[n + 1];
#pragma unroll
                for (int h = 0; h < 2; h++) {
                    float v0 = c[2 * h + 0] + b0;
                    float v1 = c[2 * h + 1] + b1;
                    uint32_t u0 = __float_as_uint(v0), u1 = __float_as_uint(v1);
                    uint32_t hi = __byte_perm(u0, u1, 0x7632);
                    float l0 = v0 - __uint_as_float(u0 & 0xFFFF0000u);
                    float l1 = v1 - __uint_as_float(u1 & 0xFFFF0000u);
                    uint32_t lo;
                    asm("cvt.rn.satfinite.bf16x2.f32 %0, %1, %2;"
                        : "=r"(lo) : "f"(l1), "f"(l0));
                    const size_t o = (size_t)(m + 8 * h) * ldc + n;
                    *(uint32_t*)((char*)Ch + o * 2) = hi;
                    *(uint32_t*)((char*)Cl + o * 2) = lo;
                }
            }
        }
    }
}

// ============================================================================
// elementwise fp32 -> (hi, lo) bf16 split, float4 per thread
// ============================================================================
__global__ __launch_bounds__(256) void split_f32(const float* __restrict__ in,
                                                 bf16* __restrict__ h,
                                                 bf16* __restrict__ l, int n4)
{
    int i = blockIdx.x * 256 + threadIdx.x;
    if (i >= n4) return;
    float4 v = ((const float4*)in)[i];
    uint32_t u0 = __float_as_uint(v.x), u1 = __float_as_uint(v.y);
    uint32_t u2 = __float_as_uint(v.z), u3 = __float_as_uint(v.w);
    uint32_t h01 = __byte_perm(u0, u1, 0x7632);
    uint32_t h23 = __byte_perm(u2, u3, 0x7632);
    float l0 = v.x - __uint_as_float(u0 & 0xFFFF0000u);
    float l1 = v.y - __uint_as_float(u1 & 0xFFFF0000u);
    float l2 = v.z - __uint_as_float(u2 & 0xFFFF0000u);
    float l3 = v.w - __uint_as_float(u3 & 0xFFFF0000u);
    uint32_t l01, l23;
    asm("cvt.rn.satfinite.bf16x2.f32 %0, %1, %2;" : "=r"(l01) : "f"(l1), "f"(l0));
    asm("cvt.rn.satfinite.bf16x2.f32 %0, %1, %2;" : "=r"(l23) : "f"(l3), "f"(l2));
    ((uint2*)h)[i] = make_uint2(h01, h23);
    ((uint2*)l)[i] = make_uint2(l01, l23);
}

// ============================================================================
// W[K,N] fp32 -> Wt hi/lo bf16 [N,K]
// ============================================================================
__global__ void transpose_split(const float* __restrict__ W,
                                bf16* __restrict__ Th, bf16* __restrict__ Tl)
{
    __shared__ float t[32][33];
    const int tx = threadIdx.x, ty = threadIdx.y;
    const int n0 = blockIdx.x * 32, k0 = blockIdx.y * 32;
#pragma unroll
    for (int r = 0; r < 32; r += 8)
        t[ty + r][tx] = W[(size_t)(k0 + ty + r) * KDIM + n0 + tx];
    __syncthreads();
#pragma unroll
    for (int r = 0; r < 32; r += 8) {
        float v = t[tx][ty + r];
        uint32_t u = __float_as_uint(v);
        size_t o = (size_t)(n0 + ty + r) * KDIM + k0 + tx;
        Th[o] = __ushort_as_bfloat16((unsigned short)(u >> 16));
        Tl[o] = __float2bfloat16(v - __uint_as_float(u & 0xFFFF0000u));
    }
}

// ============================================================================
// Row stats: for each row of S, compute rowmax and 1/sum(exp(.-rowmax)).
// P is never materialized; col_mean_fused recomputes exp on the fly.
// ============================================================================
__global__ __launch_bounds__(256) void row_stats(const float* __restrict__ S,
                                                 float* __restrict__ rmax,
                                                 float* __restrict__ rinv)
{
    __shared__ float buf[SEQ];
    __shared__ float red[256];
    const int tid = threadIdx.x;
    const float* p = S + (size_t)blockIdx.x * SEQ;

    float lmax = -1e30f;
    for (int i = tid; i < SEQ; i += 256) {
        float v = p[i];
        buf[i] = v;
        lmax = fmaxf(lmax, v);
    }
    red[tid] = lmax;
    __syncthreads();
#pragma unroll
    for (int s = 128; s > 0; s >>= 1) {
        if (tid < s) red[tid] = fmaxf(red[tid], red[tid + s]);
        __syncthreads();
    }
    const float m = red[0];
    __syncthreads();

    float lsum = 0.0f;
    for (int i = tid; i < SEQ; i += 256)
        lsum += __expf(buf[i] - m);
    red[tid] = lsum;
    __syncthreads();
#pragma unroll
    for (int s = 128; s > 0; s >>= 1) {
        if (tid < s) red[tid] += red[tid + s];
        __syncthreads();
    }
    if (tid == 0) {
        rmax[blockIdx.x] = m;
        rinv[blockIdx.x] = 1.0f / red[0];
    }
}

// ============================================================================
// Fused column mean of softmax without materializing P:
// w[b,m] = (1/SEQ) * sum_n exp(S[b,n,m] - rmax[n]) * rinv[n]
// Row stats broadcast from smem; S read column-contiguous (coalesced over m).
// ============================================================================
__global__ __launch_bounds__(256) void col_mean_fused(const float* __restrict__ S,
                                                      const float* __restrict__ rmax,
                                                      const float* __restrict__ rinv,
                                                      float* __restrict__ w)
{
    __shared__ float sm_m[SEQ];
    __shared__ float sm_i[SEQ];
    const int b = blockIdx.y;
    const int tid = threadIdx.x;
    const int m = blockIdx.x * 256 + tid;

    for (int i = tid; i < SEQ; i += 256) {
        sm_m[i] = rmax[b * SEQ + i];
        sm_i[i] = rinv[b * SEQ + i];
    }
    __syncthreads();

    const float* p = S + (size_t)b * SEQ * SEQ + m;
    float a0 = 0.f, a1 = 0.f, a2 = 0.f, a3 = 0.f;
    for (int n = 0; n < SEQ; n += 4) {
        a0 += __expf(p[(size_t)(n + 0) * SEQ] - sm_m[n + 0]) * sm_i[n + 0];
        a1 += __expf(p[(size_t)(n + 1) * SEQ] - sm_m[n + 1]) * sm_i[n + 1];
        a2 += __expf(p[(size_t)(n + 2) * SEQ] - sm_m[n + 2]) * sm_i[n + 2];
        a3 += __expf(p[(size_t)(n + 3) * SEQ] - sm_m[n + 3]) * sm_i[n + 3];
    }
    w[b * SEQ + m] = ((a0 + a1) + (a2 + a3)) * (1.0f / SEQ);
}

// ============================================================================
__global__ __launch_bounds__(256) void weighted_v(const float* __restrict__ V,
                                                  const float* __restrict__ w,
                                                  float* __restrict__ pool)
{
    const int b = blockIdx.y;
    const int d = blockIdx.x * 256 + threadIdx.x;
    const float* vp = V + (size_t)b * SEQ * KDIM + d;
    const float* wp = w + b * SEQ;
    float a0 = 0.f, a1 = 0.f, a2 = 0.f, a3 = 0.f;
    for (int m = 0; m < SEQ; m += 4) {
        a0 = fmaf(wp[m + 0], vp[(size_t)(m + 0) * KDIM], a0);
        a1 = fmaf(wp[m + 1], vp[(size_t)(m + 1) * KDIM], a1);
        a2 = fmaf(wp[m + 2], vp[(size_t)(m + 2) * KDIM], a2);
        a3 = fmaf(wp[m + 3], vp[(size_t)(m + 3) * KDIM], a3);
    }
    pool[b * KDIM + d] = (a0 + a1) + (a2 + a3);
}

__global__ void classify(const float* __restrict__ pool,
                         const float* __restrict__ Wc,
                         const float* __restrict__ bc,
                         float* __restrict__ out)
{
    const int t = threadIdx.x;
    if (t >= BATCH * NCLS) return;
    const int b = t / NCLS, c = t % NCLS;
    float acc = bc[c];
    for (int d = 0; d < KDIM; d++)
        acc = fmaf(pool[b * KDIM + d], Wc[d * NCLS + c], acc);
    out[t] = fmaxf(acc, 0.0f);
}

// ============================================================================
extern "C" void kernel_launch(void* const* d_in, const int* in_sizes, int n_in,
                              void* d_out, int out_size)
{
    const float* x  = (const float*)d_in[0];
    const float* Wk = (const float*)d_in[1];
    const float* bk = (const float*)d_in[2];
    const float* Wq = (const float*)d_in[3];
    const float* bq = (const float*)d_in[4];
    const float* Wv = (const float*)d_in[5];
    const float* bv = (const float*)d_in[6];
    const float* Wc = (const float*)d_in[7];
    const float* bc = (const float*)d_in[8];
    float* out = (float*)d_out;

    bf16 *xh, *xl, *wth, *wtl, *Qh, *Ql, *Kh, *Kl;
    float *V, *S, *rmax, *rinv, *w, *pool;
    cudaGetSymbolAddress((void**)&xh, g_xh);
    cudaGetSymbolAddress((void**)&xl, g_xl);
    cudaGetSymbolAddress((void**)&wth, g_wth);
    cudaGetSymbolAddress((void**)&wtl, g_wtl);
    cudaGetSymbolAddress((void**)&Qh, g_Qh);
    cudaGetSymbolAddress((void**)&Ql, g_Ql);
    cudaGetSymbolAddress((void**)&Kh, g_Kh);
    cudaGetSymbolAddress((void**)&Kl, g_Kl);
    cudaGetSymbolAddress((void**)&V, g_V);
    cudaGetSymbolAddress((void**)&S, g_S);
    cudaGetSymbolAddress((void**)&rmax, g_rowmax);
    cudaGetSymbolAddress((void**)&rinv, g_rowinv);
    cudaGetSymbolAddress((void**)&w, g_w);
    cudaGetSymbolAddress((void**)&pool, g_pool);

    cudaFuncSetAttribute(gemm_bf16x3, cudaFuncAttributeMaxDynamicSharedMemorySize,
                         GSMEM);

    const int M = BATCH * SEQ;              // 16384
    const size_t sQK = (size_t)SEQ * KDIM;
    const size_t sS  = (size_t)SEQ * SEQ;

    // split x into hi/lo bf16
    split_f32<<<(M * KDIM / 4 + 255) / 256, 256>>>(x, xh, xl, M * KDIM / 4);

    dim3 gT(KDIM / 32, KDIM / 32), bT(32, 8);
    dim3 gProj(KDIM / 128, M / 128, 1);

    // Q projection -> Qh/Ql
    transpose_split<<<gT, bT>>>(Wq, wth, wtl);
    gemm_bf16x3<<<gProj, 256, GSMEM>>>(xh, xl, wth, wtl, KDIM, 0, 0, 0,
                                       bq, 1.0f, 0, nullptr, Qh, Ql);
    // K projection -> Kh/Kl
    transpose_split<<<gT, bT>>>(Wk, wth, wtl);
    gemm_bf16x3<<<gProj, 256, GSMEM>>>(xh, xl, wth, wtl, KDIM, 0, 0, 0,
                                       bk, 1.0f, 0, nullptr, Kh, Kl);
    // V projection -> fp32 V
    transpose_split<<<gT, bT>>>(Wv, wth, wtl);
    gemm_bf16x3<<<gProj, 256, GSMEM>>>(xh, xl, wth, wtl, KDIM, 0, 0, 0,
                                       bv, 1.0f, 1, V, nullptr, nullptr);

    // scores: S = (Q @ K^T) / 32, per batch
    dim3 gS(SEQ / 128, SEQ / 128, BATCH);
    gemm_bf16x3<<<gS, 256, GSMEM>>>(Qh, Ql, Kh, Kl, SEQ, sQK, sQK, sS,
                                    nullptr, 1.0f / 32.0f, 2, S, nullptr, nullptr);

    // softmax stats (no P materialization), fused column mean, weighted V
    row_stats<<<BATCH * SEQ, 256>>>(S, rmax, rinv);
    col_mean_fused<<<dim3(SEQ / 256, BATCH), 256>>>(S, rmax, rinv, w);
    weighted_v<<<dim3(KDIM / 256, BATCH), 256>>>(V, w, pool);
    classify<<<1, 32>>>(pool, Wc, bc, out);
}